// round 5
// baseline (speedup 1.0000x reference)
#include <cuda_runtime.h>

#define T_STEPS 168
#define IN_DIM  16
#define NH1     64
#define NH2     32
#define NG1     256
#define NG2     128
#define BATCH   4096

#define NB   28
#define BLK  512
#define GRID ((BATCH + NB - 1) / NB)   // 147

// strides: ≡ 0 mod 4 (float4 align), ≡ 4 mod 8 (conflict-free LDS.128)
#define W1_STRIDE  84
#define W2_STRIDE  100
#define IN1_STRIDE 84

#define OFF_W1   0
#define OFF_W2   (OFF_W1  + NG1 * W1_STRIDE)    // 21504
#define OFF_B1   (OFF_W2  + NG2 * W2_STRIDE)
#define OFF_B2   (OFF_B1  + NG1)
#define OFF_WFC  (OFF_B2  + NG2)
#define OFF_IN1  (OFF_WFC + 32)
#define OFF_H2   (OFF_IN1 + NB * IN1_STRIDE)    // [28][32]
#define OFF_G1   (OFF_H2  + NB * NH2)
#define OFF_G2   (OFF_G1  + NB * NG1)
#define OFF_C1   (OFF_G2  + NB * NG2)
#define OFF_C2   (OFF_C1  + NB * NH1)
#define SMEM_FLOATS (OFF_C2 + NB * NH2)         // ~53K floats ≈ 211 KB

typedef unsigned long long u64;

__device__ __forceinline__ void fma2(u64& d, u64 a, u64 b) {
    asm("fma.rn.f32x2 %0, %1, %2, %0;" : "+l"(d) : "l"(a), "l"(b));
}
__device__ __forceinline__ u64 pack2(float lo, float hi) {
    u64 r; asm("mov.b64 %0, {%1, %2};" : "=l"(r) : "f"(lo), "f"(hi)); return r;
}
__device__ __forceinline__ float pairsum(u64 v) {
    float lo, hi;
    asm("mov.b64 {%0, %1}, %2;" : "=f"(lo), "=f"(hi) : "l"(v));
    return lo + hi;
}
__device__ __forceinline__ float sigm_(float v) {          // no clamp needed
    return __fdividef(1.f, 1.f + __expf(-v));
}
__device__ __forceinline__ float tanh_(float v) {
    v = fminf(fmaxf(v, -15.f), 15.f);
    float e = __expf(2.f * v);
    return __fdividef(e - 1.f, e + 1.f);
}

extern __shared__ float smem[];

__global__ __launch_bounds__(BLK, 1)
void lstm2_pipe_kernel(const float* __restrict__ x,
                       const float* __restrict__ Wih1, const float* __restrict__ Whh1,
                       const float* __restrict__ bih1, const float* __restrict__ bhh1,
                       const float* __restrict__ Wih2, const float* __restrict__ Whh2,
                       const float* __restrict__ bih2, const float* __restrict__ bhh2,
                       const float* __restrict__ Wfc,  const float* __restrict__ bfc,
                       float* __restrict__ out)
{
    const int tid = threadIdx.x;
    const int b0  = blockIdx.x * NB;

    float* sW1  = smem + OFF_W1;
    float* sW2  = smem + OFF_W2;
    float* sB1  = smem + OFF_B1;
    float* sB2  = smem + OFF_B2;
    float* sWfc = smem + OFF_WFC;
    float* sIn1 = smem + OFF_IN1;
    float* sH2  = smem + OFF_H2;
    float* sG1  = smem + OFF_G1;
    float* sG2  = smem + OFF_G2;
    float* sC1  = smem + OFF_C1;
    float* sC2  = smem + OFF_C2;

    // ---- weights into shared ----
    for (int i = tid; i < NG1 * W1_STRIDE; i += BLK) {
        int g = i / W1_STRIDE, k = i % W1_STRIDE;
        float v = 0.f;
        if (k < IN_DIM)            v = Wih1[g * IN_DIM + k];
        else if (k < IN_DIM + NH1) v = Whh1[g * NH1 + (k - IN_DIM)];
        sW1[i] = v;
    }
    for (int i = tid; i < NG2 * W2_STRIDE; i += BLK) {
        int g = i / W2_STRIDE, k = i % W2_STRIDE;
        float v = 0.f;
        if (k < NH1)            v = Wih2[g * NH1 + k];
        else if (k < NH1 + NH2) v = Whh2[g * NH2 + (k - NH1)];
        sW2[i] = v;
    }
    if (tid < NG1) sB1[tid] = bih1[tid] + bhh1[tid];
    if (tid < NG2) sB2[tid] = bih2[tid] + bhh2[tid];
    if (tid < NH2) sWfc[tid] = Wfc[tid];
    for (int i = tid; i < NB * IN1_STRIDE; i += BLK) sIn1[i] = 0.f;
    for (int i = tid; i < NB * NH2; i += BLK) sH2[i] = 0.f;
    for (int i = tid; i < NB * NH1; i += BLK) sC1[i] = 0.f;
    for (int i = tid; i < NB * NH2; i += BLK) sC2[i] = 0.f;

    // ---- x prefetch: 112 threads, one float4 (b, k4) each ----
    const bool xact = (tid < NB * 4);
    const int  xb = tid >> 2, xk4 = tid & 3;
    const bool xval = xact && (b0 + xb) < BATCH;
    const float* xptr = x + ((long)(b0 + xb) * T_STEPS) * IN_DIM + xk4 * 4;
    float4 xreg = make_float4(0.f, 0.f, 0.f, 0.f);
    if (xval) xreg = *(const float4*)xptr;
    __syncthreads();
    if (xact) *(float4*)&sIn1[xb * IN1_STRIDE + xk4 * 4] = xreg;   // x(0)
    if (xval) xreg = *(const float4*)(xptr + IN_DIM);              // x(1)
    __syncthreads();

    // role constants
    const int p  = tid & 127;         // gate-pair index (layer1) / gate (layer2)
    const int q  = tid >> 7;          // batch quarter: 7 batches
    const float* w1a = sW1 + p * W1_STRIDE;
    const float* w1b = sW1 + (p + 128) * W1_STRIDE;
    const float  bb1a = sB1[p];
    const float  bb1b = sB1[p + 128];
    const bool   btanh1 = (p < 64);            // gate p+128 is 'g' iff p<64
    const float* w2row = sW2 + p * W2_STRIDE;
    const float  bb2   = sB2[p];
    const bool   btanh2 = (p >= 64) && (p < 96);

    const int u3  = tid & 63;         // update1: unit
    const int bq3 = tid >> 6;         // 0..7 (7 idle)
    const int u5  = tid & 31;         // update2: unit
    const int bq5 = tid >> 5;         // 0..15 (14,15 idle)

    for (int t = 0; t <= T_STEPS; t++) {
        // ================= PHASE G =================
        if (t < T_STEPS) {
            // layer-1 gates, step t: 2 gates x 7 batches
            u64 acca[7], accb[7];
#pragma unroll
            for (int b = 0; b < 7; b++) {
                acca[b] = pack2(bb1a, 0.f);
                accb[b] = pack2(bb1b, 0.f);
            }
            const float* in1q = sIn1 + (q * 7) * IN1_STRIDE;
#pragma unroll
            for (int k4 = 0; k4 < 20; k4++) {
                const ulonglong2 wa = *(const ulonglong2*)(w1a + k4 * 4);
                const ulonglong2 wb = *(const ulonglong2*)(w1b + k4 * 4);
#pragma unroll
                for (int b = 0; b < 7; b++) {
                    const ulonglong2 h = *(const ulonglong2*)(in1q + b * IN1_STRIDE + k4 * 4);
                    fma2(acca[b], wa.x, h.x);
                    fma2(acca[b], wa.y, h.y);
                    fma2(accb[b], wb.x, h.x);
                    fma2(accb[b], wb.y, h.y);
                }
            }
#pragma unroll
            for (int b = 0; b < 7; b++) {
                const int bb = q * 7 + b;
                sG1[bb * NG1 + p]       = sigm_(pairsum(acca[b]));
                const float vb = pairsum(accb[b]);
                sG1[bb * NG1 + 128 + p] = btanh1 ? tanh_(vb) : sigm_(vb);
            }
        }
        if (t >= 1) {
            // layer-2 gates, step t-1: 1 gate x 7 batches; in2 = [h1(t-1); h2(t-2)]
            u64 acc[7];
#pragma unroll
            for (int b = 0; b < 7; b++) acc[b] = pack2(bb2, 0.f);
            const float* h1q = sIn1 + (q * 7) * IN1_STRIDE + IN_DIM;  // h1(t-1)
            const float* h2q = sH2  + (q * 7) * NH2;                  // h2(t-2)
#pragma unroll
            for (int k4 = 0; k4 < 16; k4++) {
                const ulonglong2 w = *(const ulonglong2*)(w2row + k4 * 4);
#pragma unroll
                for (int b = 0; b < 7; b++) {
                    const ulonglong2 h = *(const ulonglong2*)(h1q + b * IN1_STRIDE + k4 * 4);
                    fma2(acc[b], w.x, h.x);
                    fma2(acc[b], w.y, h.y);
                }
            }
#pragma unroll
            for (int k4 = 0; k4 < 8; k4++) {
                const ulonglong2 w = *(const ulonglong2*)(w2row + 64 + k4 * 4);
#pragma unroll
                for (int b = 0; b < 7; b++) {
                    const ulonglong2 h = *(const ulonglong2*)(h2q + b * NH2 + k4 * 4);
                    fma2(acc[b], w.x, h.x);
                    fma2(acc[b], w.y, h.y);
                }
            }
#pragma unroll
            for (int b = 0; b < 7; b++) {
                const float v = pairsum(acc[b]);
                sG2[(q * 7 + b) * NG2 + p] = btanh2 ? tanh_(v) : sigm_(v);
            }
        }
        __syncthreads();                               // barrier A

        // ================= PHASE U =================
        if (t < T_STEPS) {
            // publish x(t+1), prefetch x(t+2)
            if (xact && (t + 1) < T_STEPS)
                *(float4*)&sIn1[xb * IN1_STRIDE + xk4 * 4] = xreg;
            if (xval && (t + 2) < T_STEPS)
                xreg = *(const float4*)(xptr + (long)(t + 2) * IN_DIM);

            // layer-1 cell/h update -> h1(t) into sIn1
            if (bq3 < 7) {
#pragma unroll
                for (int j = 0; j < 4; j++) {
                    const int b = bq3 * 4 + j;
                    const float i_ = sG1[b * NG1 + u3];
                    const float f_ = sG1[b * NG1 + NH1 + u3];
                    const float g_ = sG1[b * NG1 + 2 * NH1 + u3];
                    const float o_ = sG1[b * NG1 + 3 * NH1 + u3];
                    const float c  = fmaf(f_, sC1[b * NH1 + u3], i_ * g_);
                    sC1[b * NH1 + u3] = c;
                    sIn1[b * IN1_STRIDE + IN_DIM + u3] = o_ * tanh_(c);
                }
            }
        }
        if (t >= 1) {
            // layer-2 cell/h update (step t-1) -> h2(t-1) into sH2
            if (bq5 < 14) {
#pragma unroll
                for (int j = 0; j < 2; j++) {
                    const int b = bq5 * 2 + j;
                    const float i_ = sG2[b * NG2 + u5];
                    const float f_ = sG2[b * NG2 + NH2 + u5];
                    const float g_ = sG2[b * NG2 + 2 * NH2 + u5];
                    const float o_ = sG2[b * NG2 + 3 * NH2 + u5];
                    const float c  = fmaf(f_, sC2[b * NH2 + u5], i_ * g_);
                    sC2[b * NH2 + u5] = c;
                    sH2[b * NH2 + u5] = o_ * tanh_(c);
                }
            }
        }
        __syncthreads();                               // barrier B
    }

    // ---- final FC: out[b] = h2(T-1) . Wfc + bfc ----
    if (tid < NB) {
        const int bg = b0 + tid;
        if (bg < BATCH) {
            float s = bfc[0];
#pragma unroll
            for (int u = 0; u < NH2; u++)
                s = fmaf(sH2[tid * NH2 + u], sWfc[u], s);
            out[bg] = s;
        }
    }
}

extern "C" void kernel_launch(void* const* d_in, const int* in_sizes, int n_in,
                              void* d_out, int out_size)
{
    const float* x    = (const float*)d_in[0];
    const float* Wih1 = (const float*)d_in[1];
    const float* Whh1 = (const float*)d_in[2];
    const float* bih1 = (const float*)d_in[3];
    const float* bhh1 = (const float*)d_in[4];
    const float* Wih2 = (const float*)d_in[5];
    const float* Whh2 = (const float*)d_in[6];
    const float* bih2 = (const float*)d_in[7];
    const float* bhh2 = (const float*)d_in[8];
    const float* Wfc  = (const float*)d_in[9];
    const float* bfc  = (const float*)d_in[10];
    float* out = (float*)d_out;

    const size_t smem_bytes = SMEM_FLOATS * sizeof(float);
    cudaFuncSetAttribute(lstm2_pipe_kernel,
                         cudaFuncAttributeMaxDynamicSharedMemorySize,
                         (int)smem_bytes);

    lstm2_pipe_kernel<<<GRID, BLK, smem_bytes>>>(
        x, Wih1, Whh1, bih1, bhh1, Wih2, Whh2, bih2, bhh2, Wfc, bfc, out);
}

// round 6
// speedup vs baseline: 4.3902x; 4.3902x over previous
#include <cuda_runtime.h>

// Problem constants
#define T_STEPS 168
#define IN_DIM  16
#define NH1     64
#define NH2     32
#define NG1     256   // 4*H1
#define NG2     128   // 4*H2
#define BATCH   4096

// Tiling: one wave — 147 CTAs on 148 SMs, 512 threads each
#define NB   28
#define BLK  512
#define GRID ((BATCH + NB - 1) / NB)   // 147

// Strides (floats): ≡ 0 mod 4 (float4 align), ≡ 4 mod 8 (conflict-free LDS.128)
#define W1_STRIDE  84    // 16 (x) + 64 (h1) + 4 pad
#define W2_STRIDE  100   // 64 (h1) + 32 (h2) + 4 pad
#define IN1_STRIDE 84
#define IN2_STRIDE 100

#define OFF_W1   0
#define OFF_W2   (OFF_W1  + NG1 * W1_STRIDE)
#define OFF_B1   (OFF_W2  + NG2 * W2_STRIDE)
#define OFF_B2   (OFF_B1  + NG1)
#define OFF_WFC  (OFF_B2  + NG2)
#define OFF_IN1  (OFF_WFC + 32)
#define OFF_IN2  (OFF_IN1 + NB * IN1_STRIDE)
#define OFF_G1   (OFF_IN2 + NB * IN2_STRIDE)
#define OFF_G2   (OFF_G1  + NB * NG1)
#define OFF_C1   (OFF_G2  + NB * NG2)
#define OFF_C2   (OFF_C1  + NB * NH1)
#define SMEM_FLOATS (OFF_C2 + NB * NH2)         // 53312 floats = 213248 B

typedef unsigned long long u64;

__device__ __forceinline__ void fma2(u64& d, u64 a, u64 b) {
    asm("fma.rn.f32x2 %0, %1, %2, %0;" : "+l"(d) : "l"(a), "l"(b));
}
__device__ __forceinline__ u64 pack2(float lo, float hi) {
    u64 r; asm("mov.b64 %0, {%1, %2};" : "=l"(r) : "f"(lo), "f"(hi)); return r;
}
__device__ __forceinline__ float pairsum(u64 v) {
    float lo, hi;
    asm("mov.b64 {%0, %1}, %2;" : "=f"(lo), "=f"(hi) : "l"(v));
    return lo + hi;
}
// single-MUFU activations (MUFU.TANH, sm_75+)
__device__ __forceinline__ float tanh_(float v) {
    float r; asm("tanh.approx.f32 %0, %1;" : "=f"(r) : "f"(v)); return r;
}
__device__ __forceinline__ float sigm_(float v) {
    return fmaf(0.5f, tanh_(0.5f * v), 0.5f);
}

extern __shared__ float smem[];

__global__ __launch_bounds__(BLK, 1)
void lstm2_fused_kernel(const float* __restrict__ x,
                        const float* __restrict__ Wih1, const float* __restrict__ Whh1,
                        const float* __restrict__ bih1, const float* __restrict__ bhh1,
                        const float* __restrict__ Wih2, const float* __restrict__ Whh2,
                        const float* __restrict__ bih2, const float* __restrict__ bhh2,
                        const float* __restrict__ Wfc,  const float* __restrict__ bfc,
                        float* __restrict__ out)
{
    const int tid = threadIdx.x;
    const int b0  = blockIdx.x * NB;

    float* sW1  = smem + OFF_W1;
    float* sW2  = smem + OFF_W2;
    float* sB1  = smem + OFF_B1;
    float* sB2  = smem + OFF_B2;
    float* sWfc = smem + OFF_WFC;
    float* sIn1 = smem + OFF_IN1;
    float* sIn2 = smem + OFF_IN2;
    float* sG1  = smem + OFF_G1;
    float* sG2  = smem + OFF_G2;
    float* sC1  = smem + OFF_C1;
    float* sC2  = smem + OFF_C2;

    // ---- weights into shared (combined [x;h] rows, padded strides) ----
    for (int i = tid; i < NG1 * W1_STRIDE; i += BLK) {
        int g = i / W1_STRIDE, k = i % W1_STRIDE;
        float v = 0.f;
        if (k < IN_DIM)            v = Wih1[g * IN_DIM + k];
        else if (k < IN_DIM + NH1) v = Whh1[g * NH1 + (k - IN_DIM)];
        sW1[i] = v;
    }
    for (int i = tid; i < NG2 * W2_STRIDE; i += BLK) {
        int g = i / W2_STRIDE, k = i % W2_STRIDE;
        float v = 0.f;
        if (k < NH1)            v = Wih2[g * NH1 + k];
        else if (k < NH1 + NH2) v = Whh2[g * NH2 + (k - NH1)];
        sW2[i] = v;
    }
    if (tid < NG1) sB1[tid] = bih1[tid] + bhh1[tid];
    if (tid < NG2) sB2[tid] = bih2[tid] + bhh2[tid];
    if (tid < NH2) sWfc[tid] = Wfc[tid];
    for (int i = tid; i < NB * IN1_STRIDE; i += BLK) sIn1[i] = 0.f;
    for (int i = tid; i < NB * IN2_STRIDE; i += BLK) sIn2[i] = 0.f;
    for (int i = tid; i < NB * NH1; i += BLK) sC1[i] = 0.f;
    for (int i = tid; i < NB * NH2; i += BLK) sC2[i] = 0.f;

    // ---- x prefetch: 112 threads each own one float4 (b, k4) ----
    const bool xact = (tid < NB * (IN_DIM / 4));          // 112
    const int  xb   = tid >> 2;
    const int  xk4  = tid & 3;
    const bool xval = xact && (b0 + xb) < BATCH;
    const float* xptr = x + ((long)(b0 + xb) * T_STEPS) * IN_DIM + xk4 * 4;
    float4 xreg = make_float4(0.f, 0.f, 0.f, 0.f);
    if (xval) xreg = *(const float4*)xptr;

    __syncthreads();
    if (xact) *(float4*)&sIn1[xb * IN1_STRIDE + xk4 * 4] = xreg;   // x(0)
    if (xval) xreg = *(const float4*)(xptr + IN_DIM);              // x(1)
    __syncthreads();

    // phase 2: 512 threads = 128 gate-pairs (p, p+128) x 4 batch-quarters of 7
    const int p   = tid & 127;
    const int q2  = tid >> 7;           // 0..3
    const float* w1a = sW1 + p * W1_STRIDE;
    const float* w1b = sW1 + (p + 128) * W1_STRIDE;
    const float  bb1a = sB1[p];
    const float  bb1b = sB1[p + 128];
    const bool   b_is_tanh = (p < 64);  // gate p+128 in group 2 iff p<64

    // phase 4: 512 threads = 128 gates x 4 batch-quarters of 7
    const int g2  = tid & 127;
    const int q4  = tid >> 7;
    const float* w2row = sW2 + g2 * W2_STRIDE;
    const float  bb2   = sB2[g2];
    const int    grp2  = g2 >> 5;

    // phase 3: 448 threads = 64 units x 7 batch-groups of 4
    const int u3  = tid & 63;
    const int bq3 = tid >> 6;           // 0..7, group 7 idle
    // phase 5: 448 threads = 32 units x 14 batch-groups of 2
    const int u5  = tid & 31;
    const int bq5 = tid >> 5;           // 0..15, groups 14,15 idle

    for (int t = 0; t < T_STEPS; t++) {
        // ---- phase 2: layer-1 gates (2 gates x 7 batches per thread) ----
        {
            u64 acca[7], accb[7];
#pragma unroll
            for (int b = 0; b < 7; b++) {
                acca[b] = pack2(bb1a, 0.f);
                accb[b] = pack2(bb1b, 0.f);
            }
            const float* in1q = sIn1 + (q2 * 7) * IN1_STRIDE;
#pragma unroll 4
            for (int k4 = 0; k4 < (IN_DIM + NH1) / 4; k4++) {      // 20
                const ulonglong2 wa = *(const ulonglong2*)(w1a + k4 * 4);
                const ulonglong2 wb = *(const ulonglong2*)(w1b + k4 * 4);
#pragma unroll
                for (int b = 0; b < 7; b++) {
                    const ulonglong2 h = *(const ulonglong2*)(in1q + b * IN1_STRIDE + k4 * 4);
                    fma2(acca[b], wa.x, h.x);
                    fma2(acca[b], wa.y, h.y);
                    fma2(accb[b], wb.x, h.x);
                    fma2(accb[b], wb.y, h.y);
                }
            }
#pragma unroll
            for (int b = 0; b < 7; b++) {
                const int bb = q2 * 7 + b;
                sG1[bb * NG1 + p]       = sigm_(pairsum(acca[b]));          // groups 0,1
                const float vb = pairsum(accb[b]);
                sG1[bb * NG1 + 128 + p] = b_is_tanh ? tanh_(vb) : sigm_(vb);
            }
        }
        __syncthreads();                              // B

        // ---- phase 3: layer-1 cell/h update + x(t+1) publish ----
        if (xact && (t + 1) < T_STEPS)
            *(float4*)&sIn1[xb * IN1_STRIDE + xk4 * 4] = xreg;
        if (xval && (t + 2) < T_STEPS)
            xreg = *(const float4*)(xptr + (long)(t + 2) * IN_DIM);

        if (bq3 < 7) {
#pragma unroll
            for (int j = 0; j < 4; j++) {
                const int b = bq3 * 4 + j;
                const float i_ = sG1[b * NG1 + u3];
                const float f_ = sG1[b * NG1 + NH1 + u3];
                const float g_ = sG1[b * NG1 + 2 * NH1 + u3];
                const float o_ = sG1[b * NG1 + 3 * NH1 + u3];
                const float c  = fmaf(f_, sC1[b * NH1 + u3], i_ * g_);
                sC1[b * NH1 + u3] = c;
                const float h = o_ * tanh_(c);
                sIn1[b * IN1_STRIDE + IN_DIM + u3] = h;
                sIn2[b * IN2_STRIDE + u3]          = h;
            }
        }
        __syncthreads();                              // C

        // ---- phase 4: layer-2 gates (1 gate x 7 batches per thread) ----
        {
            u64 acc[7];
#pragma unroll
            for (int b = 0; b < 7; b++) acc[b] = pack2(bb2, 0.f);
            const float* in2q = sIn2 + (q4 * 7) * IN2_STRIDE;
#pragma unroll 4
            for (int k4 = 0; k4 < (NH1 + NH2) / 4; k4++) {         // 24
                const ulonglong2 w = *(const ulonglong2*)(w2row + k4 * 4);
#pragma unroll
                for (int b = 0; b < 7; b++) {
                    const ulonglong2 h = *(const ulonglong2*)(in2q + b * IN2_STRIDE + k4 * 4);
                    fma2(acc[b], w.x, h.x);
                    fma2(acc[b], w.y, h.y);
                }
            }
#pragma unroll
            for (int b = 0; b < 7; b++) {
                const float v = pairsum(acc[b]);
                sG2[(q4 * 7 + b) * NG2 + g2] = (grp2 == 2) ? tanh_(v) : sigm_(v);
            }
        }
        __syncthreads();                              // D

        // ---- phase 5: layer-2 cell/h update (448 threads, no trailing sync) ----
        if (bq5 < 14) {
#pragma unroll
            for (int j = 0; j < 2; j++) {
                const int b = bq5 * 2 + j;
                const float i_ = sG2[b * NG2 + u5];
                const float f_ = sG2[b * NG2 + NH2 + u5];
                const float g_ = sG2[b * NG2 + 2 * NH2 + u5];
                const float o_ = sG2[b * NG2 + 3 * NH2 + u5];
                const float c  = fmaf(f_, sC2[b * NH2 + u5], i_ * g_);
                sC2[b * NH2 + u5] = c;
                sIn2[b * IN2_STRIDE + NH1 + u5] = o_ * tanh_(c);
            }
        }
        // phase5(t) writes are ordered before phase4(t+1) reads by barriers B,C of t+1
    }

    __syncthreads();

    // ---- final FC: out[b] = h2_last . Wfc + bfc ----
    if (tid < NB) {
        const int bg = b0 + tid;
        if (bg < BATCH) {
            float s = bfc[0];
#pragma unroll
            for (int u = 0; u < NH2; u++)
                s = fmaf(sIn2[tid * IN2_STRIDE + NH1 + u], sWfc[u], s);
            out[bg] = s;
        }
    }
}

extern "C" void kernel_launch(void* const* d_in, const int* in_sizes, int n_in,
                              void* d_out, int out_size)
{
    const float* x    = (const float*)d_in[0];
    const float* Wih1 = (const float*)d_in[1];
    const float* Whh1 = (const float*)d_in[2];
    const float* bih1 = (const float*)d_in[3];
    const float* bhh1 = (const float*)d_in[4];
    const float* Wih2 = (const float*)d_in[5];
    const float* Whh2 = (const float*)d_in[6];
    const float* bih2 = (const float*)d_in[7];
    const float* bhh2 = (const float*)d_in[8];
    const float* Wfc  = (const float*)d_in[9];
    const float* bfc  = (const float*)d_in[10];
    float* out = (float*)d_out;

    const size_t smem_bytes = SMEM_FLOATS * sizeof(float);  // ~213 KB
    cudaFuncSetAttribute(lstm2_fused_kernel,
                         cudaFuncAttributeMaxDynamicSharedMemorySize,
                         (int)smem_bytes);

    lstm2_fused_kernel<<<GRID, BLK, smem_bytes>>>(
        x, Wih1, Whh1, bih1, bhh1, Wih2, Whh2, bih2, bhh2, Wfc, bfc, out);
}

// round 8
// speedup vs baseline: 5.1389x; 1.1705x over previous
#include <cuda_runtime.h>

// Problem constants
#define T_STEPS 168
#define IN_DIM  16
#define NH1     64
#define NH2     32
#define NG1     256   // 4*H1
#define NG2     128   // 4*H2
#define BATCH   4096

// Tiling: one wave — 147 CTAs on 148 SMs, 512 threads each
#define NB   28
#define BLK  512
#define GRID ((BATCH + NB - 1) / NB)   // 147

// Strides (floats): ≡ 0 mod 4 (float4 align), ≡ 4 mod 8 → conflict-free
// lane-strided LDS.128
#define W1_STRIDE  84    // 16 (x) + 64 (h1) + 4 pad
#define W2_STRIDE  100   // 64 (h1) + 32 (h2) + 4 pad
#define IN1_STRIDE 84    // [0:16]=x  [16:80]=h1
#define IN2_STRIDE 68    // [0:64]=h1 + 4 pad
#define H2_STRIDE  36    // [0:32]=h2 + 4 pad

#define OFF_W1   0
#define OFF_W2   (OFF_W1  + NG1 * W1_STRIDE)
#define OFF_B1   (OFF_W2  + NG2 * W2_STRIDE)
#define OFF_B2   (OFF_B1  + NG1)
#define OFF_WFC  (OFF_B2  + NG2)
#define OFF_IN1  (OFF_WFC + 32)
#define OFF_IN2  (OFF_IN1 + NB * IN1_STRIDE)
#define OFF_H2   (OFF_IN2 + NB * IN2_STRIDE)     // double buffer [2][28][36]
#define OFF_G1   (OFF_H2  + 2 * NB * H2_STRIDE)
#define SMEM_FLOATS (OFF_G1 + NB * NG1)          // ≈ 46.4K floats ≈ 186 KB

typedef unsigned long long u64;

__device__ __forceinline__ void fma2(u64& d, u64 a, u64 b) {
    asm("fma.rn.f32x2 %0, %1, %2, %0;" : "+l"(d) : "l"(a), "l"(b));
}
__device__ __forceinline__ u64 pack2(float lo, float hi) {
    u64 r; asm("mov.b64 %0, {%1, %2};" : "=l"(r) : "f"(lo), "f"(hi)); return r;
}
__device__ __forceinline__ float pairsum(u64 v) {
    float lo, hi;
    asm("mov.b64 {%0, %1}, %2;" : "=f"(lo), "=f"(hi) : "l"(v));
    return lo + hi;
}
// single-MUFU activations (MUFU.TANH)
__device__ __forceinline__ float tanh_(float v) {
    float r; asm("tanh.approx.f32 %0, %1;" : "=f"(r) : "f"(v)); return r;
}
__device__ __forceinline__ float sigm_(float v) {
    return fmaf(0.5f, tanh_(0.5f * v), 0.5f);
}

extern __shared__ float smem[];

__global__ __launch_bounds__(BLK, 1)
void lstm2_fused_kernel(const float* __restrict__ x,
                        const float* __restrict__ Wih1, const float* __restrict__ Whh1,
                        const float* __restrict__ bih1, const float* __restrict__ bhh1,
                        const float* __restrict__ Wih2, const float* __restrict__ Whh2,
                        const float* __restrict__ bih2, const float* __restrict__ bhh2,
                        const float* __restrict__ Wfc,  const float* __restrict__ bfc,
                        float* __restrict__ out)
{
    const int tid = threadIdx.x;
    const int b0  = blockIdx.x * NB;

    float* sW1  = smem + OFF_W1;
    float* sW2  = smem + OFF_W2;
    float* sB1  = smem + OFF_B1;
    float* sB2  = smem + OFF_B2;
    float* sWfc = smem + OFF_WFC;
    float* sIn1 = smem + OFF_IN1;
    float* sIn2 = smem + OFF_IN2;
    float* sH2  = smem + OFF_H2;
    float* sG1  = smem + OFF_G1;

    // ---- weights into shared (combined [x;h] rows, padded strides) ----
    for (int i = tid; i < NG1 * W1_STRIDE; i += BLK) {
        int g = i / W1_STRIDE, k = i % W1_STRIDE;
        float v = 0.f;
        if (k < IN_DIM)            v = Wih1[g * IN_DIM + k];
        else if (k < IN_DIM + NH1) v = Whh1[g * NH1 + (k - IN_DIM)];
        sW1[i] = v;
    }
    for (int i = tid; i < NG2 * W2_STRIDE; i += BLK) {
        int g = i / W2_STRIDE, k = i % W2_STRIDE;
        float v = 0.f;
        if (k < NH1)            v = Wih2[g * NH1 + k];
        else if (k < NH1 + NH2) v = Whh2[g * NH2 + (k - NH1)];
        sW2[i] = v;
    }
    if (tid < NG1) sB1[tid] = bih1[tid] + bhh1[tid];
    if (tid < NG2) sB2[tid] = bih2[tid] + bhh2[tid];
    if (tid < NH2) sWfc[tid] = Wfc[tid];
    for (int i = tid; i < NB * IN1_STRIDE; i += BLK) sIn1[i] = 0.f;
    for (int i = tid; i < NB * IN2_STRIDE; i += BLK) sIn2[i] = 0.f;
    for (int i = tid; i < 2 * NB * H2_STRIDE; i += BLK) sH2[i] = 0.f;

    // ---- x prefetch: 112 threads each own one float4 (b, k4) ----
    const bool xact = (tid < NB * (IN_DIM / 4));          // 112
    const int  xb   = tid >> 2;
    const int  xk4  = tid & 3;
    const bool xval = xact && (b0 + xb) < BATCH;
    const float* xptr = x + ((long)(b0 + xb) * T_STEPS) * IN_DIM + xk4 * 4;
    float4 xreg = make_float4(0.f, 0.f, 0.f, 0.f);
    if (xval) xreg = *(const float4*)xptr;

    __syncthreads();
    if (xact) *(float4*)&sIn1[xb * IN1_STRIDE + xk4 * 4] = xreg;   // x(0)
    if (xval) xreg = *(const float4*)(xptr + IN_DIM);              // x(1)
    __syncthreads();

    // ---- phase 2 mapping: 128 gate-pairs (p, p+128) x 4 batch-quarters of 7 ----
    const int p   = tid & 127;
    const int q2  = tid >> 7;           // 0..3
    const float* w1a = sW1 + p * W1_STRIDE;
    const float* w1b = sW1 + (p + 128) * W1_STRIDE;
    const float  bb1a = sB1[p];
    const float  bb1b = sB1[p + 128];
    const bool   b_is_tanh = (p < 64);  // gate p+128 is 'g' iff p<64

    // ---- phase 3 mapping: 448 threads = 64 units x 7 batch-groups of 4 ----
    const int u3  = tid & 63;
    const int bq3 = tid >> 6;           // 0..7, group 7 idle
    float c1r[4];
#pragma unroll
    for (int j = 0; j < 4; j++) c1r[j] = 0.f;

    // ---- fused phase 4+5 mapping: 256 threads ----
    // u = unit (0..31), s = pair half. Lane layout keeps weight LDS.128
    // conflict-free and puts (u,0),(u,1) at lanes differing by xor 16.
    const int uf = ((tid >> 5) & 1) * 16 + (tid & 15);   // 0..31
    const int sf = (tid >> 4) & 1;
    const int qf = tid >> 6;                             // 0..3 (tid<256)
    const int gateA = uf + sf * 32;          // 0..63   : i or f (sigmoid)
    const int gateB = uf + 64 + sf * 32;     // 64..127 : g (tanh) or o (sigmoid)
    const float* wA = sW2 + gateA * W2_STRIDE;
    const float* wB = sW2 + gateB * W2_STRIDE;
    const float  bbA = sB2[gateA];
    const float  bbB = sB2[gateB];
    float c2r[7];
#pragma unroll
    for (int j = 0; j < 7; j++) c2r[j] = 0.f;

    for (int t = 0; t < T_STEPS; t++) {
        // ---- phase 2: layer-1 gates (2 gates x 7 batches per thread) ----
        {
            u64 acca[7], accb[7];
#pragma unroll
            for (int b = 0; b < 7; b++) {
                acca[b] = pack2(bb1a, 0.f);
                accb[b] = pack2(bb1b, 0.f);
            }
            const float* in1q = sIn1 + (q2 * 7) * IN1_STRIDE;
#pragma unroll 4
            for (int k4 = 0; k4 < (IN_DIM + NH1) / 4; k4++) {      // 20
                const ulonglong2 wa = *(const ulonglong2*)(w1a + k4 * 4);
                const ulonglong2 wb = *(const ulonglong2*)(w1b + k4 * 4);
#pragma unroll
                for (int b = 0; b < 7; b++) {
                    const ulonglong2 h = *(const ulonglong2*)(in1q + b * IN1_STRIDE + k4 * 4);
                    fma2(acca[b], wa.x, h.x);
                    fma2(acca[b], wa.y, h.y);
                    fma2(accb[b], wb.x, h.x);
                    fma2(accb[b], wb.y, h.y);
                }
            }
#pragma unroll
            for (int b = 0; b < 7; b++) {
                const int bb = q2 * 7 + b;
                sG1[bb * NG1 + p]       = sigm_(pairsum(acca[b]));
                const float vb = pairsum(accb[b]);
                sG1[bb * NG1 + 128 + p] = b_is_tanh ? tanh_(vb) : sigm_(vb);
            }
        }
        __syncthreads();                              // B

        // ---- phase 3: layer-1 cell/h update (c1 in regs) + x(t+1) publish ----
        if (xact && (t + 1) < T_STEPS)
            *(float4*)&sIn1[xb * IN1_STRIDE + xk4 * 4] = xreg;
        if (xval && (t + 2) < T_STEPS)
            xreg = *(const float4*)(xptr + (long)(t + 2) * IN_DIM);

        if (bq3 < 7) {
#pragma unroll
            for (int j = 0; j < 4; j++) {
                const int b = bq3 * 4 + j;
                const float i_ = sG1[b * NG1 + u3];
                const float f_ = sG1[b * NG1 + NH1 + u3];
                const float g_ = sG1[b * NG1 + 2 * NH1 + u3];
                const float o_ = sG1[b * NG1 + 3 * NH1 + u3];
                c1r[j] = fmaf(f_, c1r[j], i_ * g_);
                const float h = o_ * tanh_(c1r[j]);
                sIn1[b * IN1_STRIDE + IN_DIM + u3] = h;
                sIn2[b * IN2_STRIDE + u3]          = h;
            }
        }
        __syncthreads();                              // C

        // ---- fused phase 4+5: layer-2 gates + cell update, 256 threads ----
        // h2 is double-buffered: read h2(t-1) from buf (t-1)&1, write h2(t)
        // to buf t&1 — disjoint regions, so the cross-warp overlap of one
        // thread's epilogue writes with another's k4-loop reads is safe.
        // No trailing barrier: overlaps with phase 2 of t+1 on warps 8-15.
        if (tid < 256) {
            u64 accA[7], accB[7];
#pragma unroll
            for (int b = 0; b < 7; b++) {
                accA[b] = pack2(bbA, 0.f);
                accB[b] = pack2(bbB, 0.f);
            }
            const float* in2q = sIn2 + (qf * 7) * IN2_STRIDE;
            const float* h2q  = sH2 + ((t + 1) & 1) * (NB * H2_STRIDE)
                                     + (qf * 7) * H2_STRIDE;        // h2(t-1)
#pragma unroll 4
            for (int k4 = 0; k4 < NH1 / 4; k4++) {                  // 16
                const ulonglong2 wa = *(const ulonglong2*)(wA + k4 * 4);
                const ulonglong2 wb = *(const ulonglong2*)(wB + k4 * 4);
#pragma unroll
                for (int b = 0; b < 7; b++) {
                    const ulonglong2 h = *(const ulonglong2*)(in2q + b * IN2_STRIDE + k4 * 4);
                    fma2(accA[b], wa.x, h.x);
                    fma2(accA[b], wa.y, h.y);
                    fma2(accB[b], wb.x, h.x);
                    fma2(accB[b], wb.y, h.y);
                }
            }
#pragma unroll 4
            for (int k4 = 0; k4 < NH2 / 4; k4++) {                  // 8
                const ulonglong2 wa = *(const ulonglong2*)(wA + NH1 + k4 * 4);
                const ulonglong2 wb = *(const ulonglong2*)(wB + NH1 + k4 * 4);
#pragma unroll
                for (int b = 0; b < 7; b++) {
                    const ulonglong2 h = *(const ulonglong2*)(h2q + b * H2_STRIDE + k4 * 4);
                    fma2(accA[b], wa.x, h.x);
                    fma2(accA[b], wa.y, h.y);
                    fma2(accB[b], wb.x, h.x);
                    fma2(accB[b], wb.y, h.y);
                }
            }
            float* h2w = sH2 + (t & 1) * (NB * H2_STRIDE)
                             + (qf * 7) * H2_STRIDE;                // h2(t)
#pragma unroll
            for (int j = 0; j < 7; j++) {
                const float vA = sigm_(pairsum(accA[j]));           // i or f
                const float vBr = pairsum(accB[j]);
                const float vB = (sf == 0) ? tanh_(vBr) : sigm_(vBr); // g or o
                const float pA = __shfl_xor_sync(0xffffffffu, vA, 16);
                const float pB = __shfl_xor_sync(0xffffffffu, vB, 16);
                const float i_ = (sf == 0) ? vA : pA;
                const float f_ = (sf == 0) ? pA : vA;
                const float g_ = (sf == 0) ? vB : pB;
                const float o_ = (sf == 0) ? pB : vB;
                c2r[j] = fmaf(f_, c2r[j], i_ * g_);
                const float h = o_ * tanh_(c2r[j]);
                if ((j & 1) == sf)
                    h2w[j * H2_STRIDE + uf] = h;
            }
        }
    }

    __syncthreads();

    // ---- final FC: out[b] = h2(T-1) . Wfc + bfc ; h2(T-1) in buf (T-1)&1 ----
    if (tid < NB) {
        const int bg = b0 + tid;
        if (bg < BATCH) {
            const float* h2f = sH2 + ((T_STEPS - 1) & 1) * (NB * H2_STRIDE)
                                   + tid * H2_STRIDE;
            float s = bfc[0];
#pragma unroll
            for (int u = 0; u < NH2; u++)
                s = fmaf(h2f[u], sWfc[u], s);
            out[bg] = s;
        }
    }
}

extern "C" void kernel_launch(void* const* d_in, const int* in_sizes, int n_in,
                              void* d_out, int out_size)
{
    const float* x    = (const float*)d_in[0];
    const float* Wih1 = (const float*)d_in[1];
    const float* Whh1 = (const float*)d_in[2];
    const float* bih1 = (const float*)d_in[3];
    const float* bhh1 = (const float*)d_in[4];
    const float* Wih2 = (const float*)d_in[5];
    const float* Whh2 = (const float*)d_in[6];
    const float* bih2 = (const float*)d_in[7];
    const float* bhh2 = (const float*)d_in[8];
    const float* Wfc  = (const float*)d_in[9];
    const float* bfc  = (const float*)d_in[10];
    float* out = (float*)d_out;

    const size_t smem_bytes = SMEM_FLOATS * sizeof(float);  // ~186 KB
    cudaFuncSetAttribute(lstm2_fused_kernel,
                         cudaFuncAttributeMaxDynamicSharedMemorySize,
                         (int)smem_bytes);

    lstm2_fused_kernel<<<GRID, BLK, smem_bytes>>>(
        x, Wih1, Whh1, bih1, bhh1, Wih2, Whh2, bih2, bhh2, Wfc, bfc, out);
}